// round 17
// baseline (speedup 1.0000x reference)
#include <cuda_runtime.h>
#include <math.h>

// Problem constants
#define NTHREADS 256
#define BATCH    128
#define TLEN     129
#define NSTEP    128   // TLEN-1
#define NWIN     16    // (TLEN-1)/8
#define OUTN     32

// ---- shared memory layout (float offsets) ----
// ALL weights live in per-thread registers (packed f32x2).
// Thread t = 4r+q (r<64,q<4) owns rows {r, r+64} of V0/V1/V2[0:128],
// row 128+r of V2[128:192], K-quarter q (float4 indices 4i+q).
#define OFF_R    0        // 2048  (R row-major 32x64)
#define OFF_RB   2048     // 32
#define OFF_C0   2080     // 128
#define OFF_C1   2208     // 128
#define OFF_C2   2336     // 192
#define OFF_Y    2528     // 64
#define OFF_Y2   2592     // 64
#define OFF_S0   2656     // 128
#define OFF_S1   2784     // 128
#define OFF_M    2912     // 192
#define OFF_TN0  3104     // 3*128
#define OFF_TN1  3488     // 3*128
#define OFF_SLP  3872     // 16*8 (6 used per window)
#define OFF_DTS  4000     // 128
#define SMEM_FLOATS 4128
#define SMEM_BYTES  (SMEM_FLOATS * 4)

typedef unsigned long long u64;

// ---- fast transcendentals (MUFU-based; rel err ~1e-7, budget is 1e-3) ----
__device__ __forceinline__ float frcp_(float x) {
    float r;
    asm("rcp.approx.ftz.f32 %0, %1;" : "=f"(r) : "f"(x));
    return r;
}
// softplus + sigmoid sharing one exp:
//   e = exp(-|u|); sp = max(u,0)+log(1+e); sig = u>0 ? 1/(1+e) : e/(1+e)
__device__ __forceinline__ void sp_sig(float u, float& sp, float& g) {
    float e = __expf(-fabsf(u));
    float den = frcp_(1.0f + e);
    sp = fmaxf(u, 0.0f) + __logf(1.0f + e);
    g = (u > 0.0f) ? den : e * den;
}
// tanh + (1-tanh^2):  m = 1 - 2/(1+exp(2z))  (overflow -> inf -> rcp=0 -> m=1)
__device__ __forceinline__ void tanh_tz(float z, float& m, float& tz) {
    float e2 = __expf(2.0f * z);
    float w = frcp_(1.0f + e2);
    m = fmaf(-2.0f, w, 1.0f);
    tz = 1.0f - m * m;
}
__device__ __forceinline__ float ftanh(float z) {
    float e2 = __expf(2.0f * z);
    return fmaf(-2.0f, frcp_(1.0f + e2), 1.0f);
}

// packed f32x2 fma: lanewise d = a*b + c
__device__ __forceinline__ u64 ffma2(u64 a, u64 b, u64 c) {
    u64 d;
    asm("fma.rn.f32x2 %0, %1, %2, %3;" : "=l"(d) : "l"(a), "l"(b), "l"(c));
    return d;
}
// horizontal add of the two f32 lanes
__device__ __forceinline__ float hadd2(u64 v) {
    unsigned lo, hi;
    asm("mov.b64 {%0, %1}, %2;" : "=r"(lo), "=r"(hi) : "l"(v));
    return __uint_as_float(lo) + __uint_as_float(hi);
}
// LDS.128 into two packed f32x2 (64-bit register pairs) — loads FOUR floats p[0..3]
__device__ __forceinline__ void lds_v2u64(const float* p, u64& a, u64& b) {
    unsigned addr = (unsigned)__cvta_generic_to_shared(p);
    asm volatile("ld.shared.v2.u64 {%0, %1}, [%2];" : "=l"(a), "=l"(b) : "r"(addr));
}
// standard butterfly reduce over 4 consecutive lanes (result valid in ALL lanes)
__device__ __forceinline__ float qred(float s) {
    s += __shfl_xor_sync(0xffffffffu, s, 1);
    s += __shfl_xor_sync(0xffffffffu, s, 2);
    return s;
}
// value-routed quad reduce of a row-pair (ea: row A partial, eb: row B partial).
// Returns my-parity row's FULL quad sum: even lanes -> sum(ea), odd -> sum(eb).
// Tree is (q0+q1)+(q2+q3), identical to qred.
__device__ __forceinline__ float qred_routed(float ea, float eb, int par) {
    float send = par ? ea : eb;
    float recv = __shfl_xor_sync(0xffffffffu, send, 1);
    float kept = (par ? eb : ea) + recv;
    kept += __shfl_xor_sync(0xffffffffu, kept, 2);
    return kept;
}

// Persistent per-thread register-resident weights
struct FState {
    u64 w0[16];   // V0 rows r,r+64   : [row01*8  + 2i + j], i<4
    u64 w1[32];   // V1 rows r,r+64   : [row01*16 + 2i + j], i<8
    u64 w2a[32];  // V2 rows r,r+64   : [row01*16 + 2i + j], i<8
    u64 w2b[16];  // V2 row 128+r     : [2i + j], i<8
};

// F(y) . s. 256 threads, row-pair x quarter-K split, all weights in registers.
// Parity-routed reductions: even lanes carry row r, odd lanes row r+64.
// Returns k[r] valid on EVEN lanes (caller uses q==0).
// NO trailing barrier — caller must __syncthreads() after consuming k.
__device__ __forceinline__ float eval_F(float* sm, int tid,
                                        const float* __restrict__ yin,
                                        const float* __restrict__ svec,
                                        const FState& W)
{
    const int r = tid >> 2, q = tid & 3;
    const int par = q & 1;                   // 0: row r, 1: row r+64
    const int rowoff = par ? 64 : 0;
    float* s0  = sm + OFF_S0;
    float* s1  = sm + OFF_S1;
    float* msm = sm + OFF_M;
    float* tn0 = sm + OFF_TN0;
    float* tn1 = sm + OFF_TN1;

    float g0p, g1p;            // sigmoid gates for my parity row
    float m_ab, tz_ab;         // tanh for my parity row
    float mc, tzc;             // tanh row 128+r (all lanes)

    // ---------- forward layer 0: u0 = V0 @ y + c0 (K=64) ----------
    {
        float bias = sm[OFF_C0 + r + rowoff];   // prefetch: hides under body
        u64 acc0 = 0ull, acc1 = 0ull;
#pragma unroll
        for (int i = 0; i < 4; i++) {
            u64 a0, a1;
            lds_v2u64(yin + (4 * i + q) * 4, a0, a1);
            acc0 = ffma2(W.w0[2 * i], a0, acc0);
            acc0 = ffma2(W.w0[2 * i + 1], a1, acc0);
            acc1 = ffma2(W.w0[8 + 2 * i], a0, acc1);
            acc1 = ffma2(W.w0[8 + 2 * i + 1], a1, acc1);
        }
        float kept = qred_routed(hadd2(acc0), hadd2(acc1), par);
        float u = bias + kept;
        float sp;
        sp_sig(u, sp, g0p);
        if (q < 2) s0[r + q * 64] = sp;
    }
    __syncthreads();
    // ---------- forward layer 1 (K=128) ----------
    {
        float bias = sm[OFF_C1 + r + rowoff];
        u64 acc0 = 0ull, acc1 = 0ull;
#pragma unroll
        for (int i = 0; i < 8; i++) {
            u64 a0, a1;
            lds_v2u64(s0 + (4 * i + q) * 4, a0, a1);
            acc0 = ffma2(W.w1[2 * i], a0, acc0);
            acc0 = ffma2(W.w1[2 * i + 1], a1, acc0);
            acc1 = ffma2(W.w1[16 + 2 * i], a0, acc1);
            acc1 = ffma2(W.w1[16 + 2 * i + 1], a1, acc1);
        }
        float kept = qred_routed(hadd2(acc0), hadd2(acc1), par);
        float u = bias + kept;
        float sp;
        sp_sig(u, sp, g1p);
        if (q < 2) s1[r + q * 64] = sp;
    }
    __syncthreads();
    // ---------- forward layer 2 (192 rows: r/r+64 routed, 128+r all-lane) ----------
    {
        float biasab = sm[OFF_C2 + r + rowoff];
        float biasc  = sm[OFF_C2 + 128 + r];
        u64 acc0 = 0ull, acc1 = 0ull, acc2 = 0ull;
#pragma unroll
        for (int i = 0; i < 8; i++) {
            u64 a0, a1;
            lds_v2u64(s1 + (4 * i + q) * 4, a0, a1);
            acc0 = ffma2(W.w2a[2 * i], a0, acc0);
            acc0 = ffma2(W.w2a[2 * i + 1], a1, acc0);
            acc1 = ffma2(W.w2a[16 + 2 * i], a0, acc1);
            acc1 = ffma2(W.w2a[16 + 2 * i + 1], a1, acc1);
            acc2 = ffma2(W.w2b[2 * i], a0, acc2);
            acc2 = ffma2(W.w2b[2 * i + 1], a1, acc2);
        }
        float kab = qred_routed(hadd2(acc0), hadd2(acc1), par);
        float sc  = qred(hadd2(acc2));
        tanh_tz(biasab + kab, m_ab, tz_ab);
        tanh_tz(biasc + sc, mc, tzc);
        if (q < 2) msm[r + q * 64] = m_ab;
        if (q == 0) msm[128 + r] = mc;
    }
    __syncthreads();
    // ---------- JVP layer 0 (3 tangents = rows of m; K=64) ----------
    {
        u64 d00 = 0ull, d01 = 0ull, d02 = 0ull;
        u64 d10 = 0ull, d11 = 0ull, d12 = 0ull;
#pragma unroll
        for (int i = 0; i < 4; i++) {
            u64 a0, a1, b0, b1, c0v, c1v;
            lds_v2u64(msm + (4 * i + q) * 4, a0, a1);
            lds_v2u64(msm + 64 + (4 * i + q) * 4, b0, b1);
            lds_v2u64(msm + 128 + (4 * i + q) * 4, c0v, c1v);
            u64 wa0 = W.w0[2 * i], wa1 = W.w0[2 * i + 1];
            u64 wb0 = W.w0[8 + 2 * i], wb1 = W.w0[8 + 2 * i + 1];
            d00 = ffma2(wa0, a0, d00);  d00 = ffma2(wa1, a1, d00);
            d01 = ffma2(wa0, b0, d01);  d01 = ffma2(wa1, b1, d01);
            d02 = ffma2(wa0, c0v, d02); d02 = ffma2(wa1, c1v, d02);
            d10 = ffma2(wb0, a0, d10);  d10 = ffma2(wb1, a1, d10);
            d11 = ffma2(wb0, b0, d11);  d11 = ffma2(wb1, b1, d11);
            d12 = ffma2(wb0, c0v, d12); d12 = ffma2(wb1, c1v, d12);
        }
        float k0 = qred_routed(hadd2(d00), hadd2(d10), par);
        float k1 = qred_routed(hadd2(d01), hadd2(d11), par);
        float k2 = qred_routed(hadd2(d02), hadd2(d12), par);
        if (q < 2) {
            int base = r + q * 64;
            tn0[base]       = g0p * k0;
            tn0[128 + base] = g0p * k1;
            tn0[256 + base] = g0p * k2;
        }
    }
    __syncthreads();
    // ---------- JVP layer 1 (K=128) ----------
    {
        u64 d00 = 0ull, d01 = 0ull, d02 = 0ull;
        u64 d10 = 0ull, d11 = 0ull, d12 = 0ull;
#pragma unroll
        for (int i = 0; i < 8; i++) {
            u64 a0, a1, b0, b1, c0v, c1v;
            lds_v2u64(tn0 + (4 * i + q) * 4, a0, a1);
            lds_v2u64(tn0 + 128 + (4 * i + q) * 4, b0, b1);
            lds_v2u64(tn0 + 256 + (4 * i + q) * 4, c0v, c1v);
            u64 wa0 = W.w1[2 * i], wa1 = W.w1[2 * i + 1];
            u64 wb0 = W.w1[16 + 2 * i], wb1 = W.w1[16 + 2 * i + 1];
            d00 = ffma2(wa0, a0, d00);  d00 = ffma2(wa1, a1, d00);
            d01 = ffma2(wa0, b0, d01);  d01 = ffma2(wa1, b1, d01);
            d02 = ffma2(wa0, c0v, d02); d02 = ffma2(wa1, c1v, d02);
            d10 = ffma2(wb0, a0, d10);  d10 = ffma2(wb1, a1, d10);
            d11 = ffma2(wb0, b0, d11);  d11 = ffma2(wb1, b1, d11);
            d12 = ffma2(wb0, c0v, d12); d12 = ffma2(wb1, c1v, d12);
        }
        float k0 = qred_routed(hadd2(d00), hadd2(d10), par);
        float k1 = qred_routed(hadd2(d01), hadd2(d11), par);
        float k2 = qred_routed(hadd2(d02), hadd2(d12), par);
        if (q < 2) {
            int base = r + q * 64;
            tn1[base]       = g1p * k0;
            tn1[128 + base] = g1p * k1;
            tn1[256 + base] = g1p * k2;
        }
    }
    __syncthreads();
    // ---------- JVP layer 2 — only the 6 J-blocks the bracket uses ----------
    // All-lane qreds here: the 6 terms must meet in one lane for the bracket.
    {
        // prefetch svec early so LDS latency hides under the FFMA body
        float sv0 = svec[0], sv1 = svec[1], sv2 = svec[2];
        float sv3 = svec[3], sv4 = svec[4], sv5 = svec[5];
        u64 d01 = 0ull, d02 = 0ull;    // row r       x tangents 1,2
        u64 d10 = 0ull, d12 = 0ull;    // row r+64    x tangents 0,2
        u64 d20 = 0ull, d21 = 0ull;    // row 128+r   x tangents 0,1
#pragma unroll
        for (int i = 0; i < 8; i++) {
            u64 a0, a1, b0, b1, c0v, c1v;
            lds_v2u64(tn1 + (4 * i + q) * 4, a0, a1);
            lds_v2u64(tn1 + 128 + (4 * i + q) * 4, b0, b1);
            lds_v2u64(tn1 + 256 + (4 * i + q) * 4, c0v, c1v);
            u64 wa0 = W.w2a[2 * i], wa1 = W.w2a[2 * i + 1];
            u64 wb0 = W.w2a[16 + 2 * i], wb1 = W.w2a[16 + 2 * i + 1];
            u64 wc0 = W.w2b[2 * i], wc1 = W.w2b[2 * i + 1];
            d01 = ffma2(wa0, b0, d01);  d01 = ffma2(wa1, b1, d01);
            d02 = ffma2(wa0, c0v, d02); d02 = ffma2(wa1, c1v, d02);
            d10 = ffma2(wb0, a0, d10);  d10 = ffma2(wb1, a1, d10);
            d12 = ffma2(wb0, c0v, d12); d12 = ffma2(wb1, c1v, d12);
            d20 = ffma2(wc0, a0, d20);  d20 = ffma2(wc1, a1, d20);
            d21 = ffma2(wc0, b0, d21);  d21 = ffma2(wc1, b1, d21);
        }
        float e01 = qred(hadd2(d01)), e02 = qred(hadd2(d02));
        float e10 = qred(hadd2(d10)), e12 = qred(hadd2(d12));
        float e20 = qred(hadd2(d20)), e21 = qred(hadd2(d21));
        // gather row-(r+64) tanh state onto even lanes
        float mb_  = __shfl_xor_sync(0xffffffffu, m_ab, 1);
        float tzb_ = __shfl_xor_sync(0xffffffffu, tz_ab, 1);
        // valid on EVEN lanes: m_ab=ma, tz_ab=tza, mb_=mb, tzb_=tzb
        float br01 = tzb_ * e10 - tz_ab * e01;
        float br02 = tzc  * e20 - tz_ab * e02;
        float br12 = tzc  * e21 - tzb_ * e12;
        float k =  m_ab * sv0 + mb_ * sv1 + mc * sv2
                 + br01 * sv3 + br02 * sv4 + br12 * sv5;
        return k;   // valid on even lanes; caller predicates on q==0
    }
}

// Output projection: out_row[o] = tanh(dot(y, R[o,:]) + rb[o])
// 256 threads: 8 threads per output, 8-dim partials.
// Each thread loads its 8 floats as 2x(LDS.128 = 4 floats) per operand.
__device__ __forceinline__ void write_out_row(const float* sm, int t, float* __restrict__ dst)
{
    int o = t >> 3, part = t & 7;
    const float* rp = sm + OFF_R + o * 64 + part * 8;
    const float* yp = sm + OFF_Y + part * 8;
    u64 r0, r1, r2, r3, y0, y1, y2, y3;
    lds_v2u64(rp,     r0, r1);
    lds_v2u64(rp + 4, r2, r3);
    lds_v2u64(yp,     y0, y1);
    lds_v2u64(yp + 4, y2, y3);
    u64 acc = ffma2(r0, y0, 0ull);
    acc = ffma2(r1, y1, acc);
    acc = ffma2(r2, y2, acc);
    acc = ffma2(r3, y3, acc);
    float s = hadd2(acc);
    s += __shfl_xor_sync(0xffffffffu, s, 1);
    s += __shfl_xor_sync(0xffffffffu, s, 2);
    s += __shfl_xor_sync(0xffffffffu, s, 4);
    if (part == 0) dst[o] = ftanh(s + sm[OFF_RB + o]);
}

__global__ void __launch_bounds__(NTHREADS, 1)
ncde_kernel(const float* __restrict__ ts, const float* __restrict__ x,
            const float* __restrict__ W0, const float* __restrict__ b0,
            const float* __restrict__ W1, const float* __restrict__ b1,
            const float* __restrict__ W2, const float* __restrict__ b2,
            const float* __restrict__ V0, const float* __restrict__ c0,
            const float* __restrict__ V1, const float* __restrict__ c1,
            const float* __restrict__ V2, const float* __restrict__ c2,
            const float* __restrict__ R,  const float* __restrict__ rb,
            float* __restrict__ out)
{
    extern __shared__ float sm[];
    const int t = threadIdx.x;
    const int b = blockIdx.x;
    const int r = t >> 2, q = t & 3;

    // ---- pin per-thread weight slices in registers (packed f32x2) ----
    FState W;
#pragma unroll
    for (int ro = 0; ro < 2; ro++) {
        int row = r + 64 * ro;
#pragma unroll
        for (int i = 0; i < 4; i++) {
            ulonglong2 v = *(const ulonglong2*)(V0 + row * 64 + (4 * i + q) * 4);
            W.w0[ro * 8 + 2 * i] = v.x; W.w0[ro * 8 + 2 * i + 1] = v.y;
        }
#pragma unroll
        for (int i = 0; i < 8; i++) {
            ulonglong2 v = *(const ulonglong2*)(V1 + row * 128 + (4 * i + q) * 4);
            W.w1[ro * 16 + 2 * i] = v.x; W.w1[ro * 16 + 2 * i + 1] = v.y;
        }
#pragma unroll
        for (int i = 0; i < 8; i++) {
            ulonglong2 v = *(const ulonglong2*)(V2 + row * 128 + (4 * i + q) * 4);
            W.w2a[ro * 16 + 2 * i] = v.x; W.w2a[ro * 16 + 2 * i + 1] = v.y;
        }
    }
#pragma unroll
    for (int i = 0; i < 8; i++) {
        ulonglong2 v = *(const ulonglong2*)(V2 + (128 + r) * 128 + (4 * i + q) * 4);
        W.w2b[2 * i] = v.x; W.w2b[2 * i + 1] = v.y;
    }

    // ---- stage small constants into SMEM ----
    for (int i = t; i < 2048; i += NTHREADS) sm[OFF_R + i] = R[i];
    if (t < 32) sm[OFF_RB + t] = rb[t];
    if (t < 128) { sm[OFF_C0 + t] = c0[t]; sm[OFF_C1 + t] = c1[t]; }
    if (t < 192) sm[OFF_C2 + t] = c2[t];

    // ---- per-batch: dt array ----
    {
        const float* tsb = ts + b * TLEN;
        for (int i = t; i < NSTEP; i += NTHREADS) sm[OFF_DTS + i] = tsb[i + 1] - tsb[i];
    }

    // ---- per-batch: window log-signature slopes (16 windows x 6 channels) ----
    if (t < NWIN) {
        const float* xp = x + (b * TLEN + t * 8) * 3;
        float p[9][3];
#pragma unroll
        for (int k = 0; k < 9; k++) {
            p[k][0] = xp[k * 3 + 0];
            p[k][1] = xp[k * 3 + 1];
            p[k][2] = xp[k * 3 + 2];
        }
        float a01 = 0.f, a10 = 0.f, a02 = 0.f, a20 = 0.f, a12 = 0.f, a21 = 0.f;
#pragma unroll
        for (int k = 0; k < 8; k++) {
            float r0 = p[k][0] - p[0][0], r1 = p[k][1] - p[0][1], r2 = p[k][2] - p[0][2];
            float d0 = p[k + 1][0] - p[k][0], d1 = p[k + 1][1] - p[k][1], d2 = p[k + 1][2] - p[k][2];
            a01 = fmaf(r0, d1, a01); a10 = fmaf(r1, d0, a10);
            a02 = fmaf(r0, d2, a02); a20 = fmaf(r2, d0, a20);
            a12 = fmaf(r1, d2, a12); a21 = fmaf(r2, d1, a21);
        }
        const float* tsb = ts + b * TLEN;
        float td = tsb[(t + 1) * 8] - tsb[t * 8];
        float* sl = sm + OFF_SLP + t * 8;
        sl[0] = (p[8][0] - p[0][0]) / td;
        sl[1] = (p[8][1] - p[0][1]) / td;
        sl[2] = (p[8][2] - p[0][2]) / td;
        sl[3] = (0.5f * (a01 - a10)) / td;
        sl[4] = (0.5f * (a02 - a20)) / td;
        sl[5] = (0.5f * (a12 - a21)) / td;
    }
    __syncthreads();

    // ---- init MLP: h0 = W2 @ sp(W1 @ sp(W0 @ x0 + b0) + b1) + b2 ----
    if (t < 128) {
        const float* xp = x + b * TLEN * 3;
        float x0 = xp[0], x1 = xp[1], x2 = xp[2];
        float u = b0[t] + W0[t * 3] * x0 + W0[t * 3 + 1] * x1 + W0[t * 3 + 2] * x2;
        float sp, gdummy;
        sp_sig(u, sp, gdummy);
        sm[OFF_S0 + t] = sp;
    }
    __syncthreads();
    if (t < 128) {
        float acc = b1[t];
        const float* w = W1 + t * 128;
#pragma unroll 4
        for (int j = 0; j < 128; j++) acc = fmaf(w[j], sm[OFF_S0 + j], acc);
        float sp, gdummy;
        sp_sig(acc, sp, gdummy);
        sm[OFF_S1 + t] = sp;
    }
    __syncthreads();
    if (t < 64) {
        float acc = b2[t];
        const float* w = W2 + t * 128;
#pragma unroll 4
        for (int j = 0; j < 128; j++) acc = fmaf(w[j], sm[OFF_S1 + j], acc);
        sm[OFF_Y + t] = acc;
    }
    __syncthreads();

    // ---- output row 0 (from h0) ----
    write_out_row(sm, t, out + (b * TLEN + 0) * OUTN);

    // register-carried state: lanes q==0 of quad r own y[r]
    float yreg = sm[OFF_Y + r];   // valid use on q==0 lanes only

    // ---- RK2 (Heun) scan over 128 steps ----
    for (int i = 0; i < NSTEP; i++) {
        float dt = sm[OFF_DTS + i];
        const float* svec = sm + OFF_SLP + ((i >> 3) << 3);

        float k1 = eval_F(sm, t, sm + OFF_Y, svec, W);
        if (q == 0) sm[OFF_Y2 + r] = fmaf(dt, k1, yreg);
        __syncthreads();

        float k2 = eval_F(sm, t, sm + OFF_Y2, svec, W);
        if (q == 0) {
            yreg = fmaf(0.5f * dt, k1 + k2, yreg);
            sm[OFF_Y + r] = yreg;
        }
        __syncthreads();

        write_out_row(sm, t, out + (b * TLEN + i + 1) * OUTN);
    }
}

extern "C" void kernel_launch(void* const* d_in, const int* in_sizes, int n_in,
                              void* d_out, int out_size)
{
    const float* ts = (const float*)d_in[0];
    const float* x  = (const float*)d_in[1];
    const float* W0 = (const float*)d_in[2];
    const float* b0 = (const float*)d_in[3];
    const float* W1 = (const float*)d_in[4];
    const float* b1 = (const float*)d_in[5];
    const float* W2 = (const float*)d_in[6];
    const float* b2 = (const float*)d_in[7];
    const float* V0 = (const float*)d_in[8];
    const float* c0 = (const float*)d_in[9];
    const float* V1 = (const float*)d_in[10];
    const float* c1 = (const float*)d_in[11];
    const float* V2 = (const float*)d_in[12];
    const float* c2 = (const float*)d_in[13];
    const float* R  = (const float*)d_in[14];
    const float* rb = (const float*)d_in[15];
    float* out = (float*)d_out;

    cudaFuncSetAttribute(ncde_kernel, cudaFuncAttributeMaxDynamicSharedMemorySize, SMEM_BYTES);
    ncde_kernel<<<BATCH, NTHREADS, SMEM_BYTES>>>(ts, x, W0, b0, W1, b1, W2, b2,
                                                 V0, c0, V1, c1, V2, c2, R, rb, out);
}